// round 2
// baseline (speedup 1.0000x reference)
#include <cuda_runtime.h>

#define DIM 128
#define NODES_MAX 50000

// Scratch (static device globals — no runtime allocation allowed)
__device__ __align__(16) float g_z[NODES_MAX * DIM];
__device__ __align__(16) float g_y[NODES_MAX * DIM];
__device__ float g_sum[DIM];
__device__ float g_sq[DIM];
__device__ float g_scale[DIM];
__device__ float g_shift[DIM];

// ---------------------------------------------------------------------------
// 1) z = (1+eps)*h  ; also zero BN stat accumulators
// ---------------------------------------------------------------------------
__global__ void init_kernel(const float* __restrict__ h,
                            const float* __restrict__ eps, int total4) {
    int i = blockIdx.x * blockDim.x + threadIdx.x;
    if (blockIdx.x == 0 && threadIdx.x < DIM) {
        g_sum[threadIdx.x] = 0.f;
        g_sq[threadIdx.x] = 0.f;
    }
    if (i < total4) {
        float e = 1.0f + eps[0];
        float4 v = ((const float4*)h)[i];
        v.x *= e; v.y *= e; v.z *= e; v.w *= e;
        ((float4*)g_z)[i] = v;
    }
}

// ---------------------------------------------------------------------------
// 2) z[dst] += h[src]  (edge-parallel scatter-add; warp per edge, lane = 4 feats)
//    Indices are int32 (JAX default x64-disabled downcasts int64 -> int32).
//    Bounds guard converts any dtype surprise into rel_err, not a crash.
// ---------------------------------------------------------------------------
__global__ void edge_kernel(const float* __restrict__ h,
                            const int* __restrict__ src,
                            const int* __restrict__ dst,
                            int nnodes, long long total) {
    long long idx = (long long)blockIdx.x * blockDim.x + threadIdx.x;
    if (idx >= total) return;
    long long e = idx >> 5;
    int lane = (int)(idx & 31);
    int s = src[e];   // broadcast across warp (same address)
    int d = dst[e];
    if ((unsigned)s >= (unsigned)nnodes || (unsigned)d >= (unsigned)nnodes) return;
    float4 v = *(const float4*)(h + (long long)s * DIM + lane * 4);
    float* p = g_z + (long long)d * DIM + lane * 4;
    atomicAdd(p + 0, v.x);
    atomicAdd(p + 1, v.y);
    atomicAdd(p + 2, v.z);
    atomicAdd(p + 3, v.w);
}

// ---------------------------------------------------------------------------
// 3/4) C = act(A @ W + b).  64-row x 128-col tile per block, K=128 in smem.
//      Warp = one row-group; A reads are LDS broadcasts, W reads LDS.128.
// ---------------------------------------------------------------------------
__global__ __launch_bounds__(256, 2)
void gemm_kernel(const float* __restrict__ A, const float* __restrict__ W,
                 const float* __restrict__ bias, float* __restrict__ C,
                 int M, int do_relu) {
    extern __shared__ float sm[];
    float* Ws = sm;              // DIM*DIM floats   (64 KB)
    float* As = sm + DIM * DIM;  // 64*DIM floats    (32 KB)
    int tid = threadIdx.x;
    int row0 = blockIdx.x * 64;

    // Load W (16384 floats = 4096 float4)
    const float4* W4 = (const float4*)W;
    float4* Ws4 = (float4*)Ws;
#pragma unroll
    for (int i = 0; i < 16; i++) Ws4[tid + 256 * i] = W4[tid + 256 * i];

    // Load A tile (64 rows x 128 = 2048 float4), zero-pad past M
    float4* As4 = (float4*)As;
#pragma unroll
    for (int i = 0; i < 8; i++) {
        int idx = tid + 256 * i;
        int r = idx >> 5;
        int c = idx & 31;
        float4 v = make_float4(0.f, 0.f, 0.f, 0.f);
        int gr = row0 + r;
        if (gr < M) v = ((const float4*)A)[(long long)gr * 32 + c];
        As4[idx] = v;
    }
    __syncthreads();

    int cg = tid & 31;   // column group -> cols [4cg, 4cg+4)
    int rg = tid >> 5;   // row group    -> rows [rg*8, rg*8+8)

    float acc[8][4];
#pragma unroll
    for (int i = 0; i < 8; i++) {
        acc[i][0] = 0.f; acc[i][1] = 0.f; acc[i][2] = 0.f; acc[i][3] = 0.f;
    }

    const float* Ar = As + rg * 8 * DIM;
#pragma unroll 4
    for (int k = 0; k < DIM; k += 4) {
        float4 w0 = *(const float4*)(Ws + (k + 0) * DIM + cg * 4);
        float4 w1 = *(const float4*)(Ws + (k + 1) * DIM + cg * 4);
        float4 w2 = *(const float4*)(Ws + (k + 2) * DIM + cg * 4);
        float4 w3 = *(const float4*)(Ws + (k + 3) * DIM + cg * 4);
#pragma unroll
        for (int i = 0; i < 8; i++) {
            float4 a = *(const float4*)(Ar + i * DIM + k);  // warp-broadcast
            acc[i][0] += a.x * w0.x + a.y * w1.x + a.z * w2.x + a.w * w3.x;
            acc[i][1] += a.x * w0.y + a.y * w1.y + a.z * w2.y + a.w * w3.y;
            acc[i][2] += a.x * w0.z + a.y * w1.z + a.z * w2.z + a.w * w3.z;
            acc[i][3] += a.x * w0.w + a.y * w1.w + a.z * w2.w + a.w * w3.w;
        }
    }

    float4 b4 = ((const float4*)bias)[cg];
#pragma unroll
    for (int i = 0; i < 8; i++) {
        int gr = row0 + rg * 8 + i;
        if (gr < M) {
            float4 o;
            o.x = acc[i][0] + b4.x;
            o.y = acc[i][1] + b4.y;
            o.z = acc[i][2] + b4.z;
            o.w = acc[i][3] + b4.w;
            if (do_relu) {
                o.x = fmaxf(o.x, 0.f); o.y = fmaxf(o.y, 0.f);
                o.z = fmaxf(o.z, 0.f); o.w = fmaxf(o.w, 0.f);
            }
            ((float4*)(C + (long long)gr * DIM))[cg] = o;
        }
    }
}

// ---------------------------------------------------------------------------
// 5) BN stats: per-column sum & sumsq (coalesced; one atomic per block/column)
// ---------------------------------------------------------------------------
#define STAT_ROWS 512
__global__ void stats_kernel(const float* __restrict__ Z, int M) {
    int col = threadIdx.x;  // 128 threads
    int r0 = blockIdx.x * STAT_ROWS;
    int r1 = min(r0 + STAT_ROWS, M);
    float s = 0.f, q = 0.f;
    for (int r = r0; r < r1; r++) {
        float v = Z[(long long)r * DIM + col];
        s += v;
        q += v * v;
    }
    atomicAdd(&g_sum[col], s);
    atomicAdd(&g_sq[col], q);
}

// ---------------------------------------------------------------------------
// 6) fold BN stats into per-column scale/shift
// ---------------------------------------------------------------------------
__global__ void bnfin_kernel(const float* __restrict__ gamma,
                             const float* __restrict__ beta, float invN) {
    int t = threadIdx.x;
    float mean = g_sum[t] * invN;
    float var = g_sq[t] * invN - mean * mean;
    float sc = gamma[t] * rsqrtf(var + 1e-5f);
    g_scale[t] = sc;
    g_shift[t] = beta[t] - mean * sc;
}

// ---------------------------------------------------------------------------
// 7) out = h + leaky_relu(z*scale + shift)
// ---------------------------------------------------------------------------
__global__ void ewise_kernel(const float* __restrict__ h,
                             const float* __restrict__ Z,
                             float* __restrict__ out, int total4) {
    int i = blockIdx.x * blockDim.x + threadIdx.x;
    if (i >= total4) return;
    int cg = i & 31;
    float4 sc = ((const float4*)g_scale)[cg];
    float4 sh = ((const float4*)g_shift)[cg];
    float4 zv = ((const float4*)Z)[i];
    float4 hv = ((const float4*)h)[i];
    float x;
    float4 o;
    x = zv.x * sc.x + sh.x; o.x = hv.x + (x >= 0.f ? x : 0.01f * x);
    x = zv.y * sc.y + sh.y; o.y = hv.y + (x >= 0.f ? x : 0.01f * x);
    x = zv.z * sc.z + sh.z; o.z = hv.z + (x >= 0.f ? x : 0.01f * x);
    x = zv.w * sc.w + sh.w; o.w = hv.w + (x >= 0.f ? x : 0.01f * x);
    ((float4*)out)[i] = o;
}

// ---------------------------------------------------------------------------
extern "C" void kernel_launch(void* const* d_in, const int* in_sizes, int n_in,
                              void* d_out, int out_size) {
    const float* h     = (const float*)d_in[0];
    const int*   src   = (const int*)d_in[1];
    const int*   dst   = (const int*)d_in[2];
    const float* eps   = (const float*)d_in[3];
    const float* W1    = (const float*)d_in[4];
    const float* b1    = (const float*)d_in[5];
    const float* W2    = (const float*)d_in[6];
    const float* b2    = (const float*)d_in[7];
    const float* gamma = (const float*)d_in[8];
    const float* beta  = (const float*)d_in[9];
    float* out = (float*)d_out;

    int N = in_sizes[0] / DIM;
    long long E = in_sizes[1];
    int total4 = N * (DIM / 4);

    size_t smem = (size_t)(DIM * DIM + 64 * DIM) * sizeof(float);  // 96 KB
    cudaFuncSetAttribute(gemm_kernel,
                         cudaFuncAttributeMaxDynamicSharedMemorySize,
                         (int)smem);

    void *zp = nullptr, *yp = nullptr;
    cudaGetSymbolAddress(&zp, g_z);
    cudaGetSymbolAddress(&yp, g_y);

    // 1) z = (1+eps)*h ; zero stats
    init_kernel<<<(total4 + 255) / 256, 256>>>(h, eps, total4);

    // 2) scatter-add edges
    long long tot = E * 32;
    edge_kernel<<<(int)((tot + 255) / 256), 256>>>(h, src, dst, N, tot);

    // 3) y = relu(z @ W1 + b1)
    int gblocks = (N + 63) / 64;
    gemm_kernel<<<gblocks, 256, smem>>>((const float*)zp, W1, b1, (float*)yp, N, 1);

    // 4) z = y @ W2 + b2
    gemm_kernel<<<gblocks, 256, smem>>>((const float*)yp, W2, b2, (float*)zp, N, 0);

    // 5) BN column stats
    stats_kernel<<<(N + STAT_ROWS - 1) / STAT_ROWS, DIM>>>((const float*)zp, N);

    // 6) fold into scale/shift
    bnfin_kernel<<<1, DIM>>>(gamma, beta, 1.0f / (float)N);

    // 7) out = h + leaky(z*scale + shift)
    ewise_kernel<<<(total4 + 255) / 256, 256>>>(h, (const float*)zp, out, total4);
}

// round 3
// speedup vs baseline: 1.7726x; 1.7726x over previous
#include <cuda_runtime.h>

#define DIM 128
#define NODES_MAX 50000

// Scratch (static device globals — no runtime allocation allowed)
__device__ __align__(16) float g_z[NODES_MAX * DIM];
__device__ __align__(16) float g_y[NODES_MAX * DIM];
__device__ float g_sum[DIM];
__device__ float g_sq[DIM];
__device__ float g_scale[DIM];
__device__ float g_shift[DIM];

// ---------------------------------------------------------------------------
// 1) z = (1+eps)*h  ; also zero BN stat accumulators
// ---------------------------------------------------------------------------
__global__ void init_kernel(const float* __restrict__ h,
                            const float* __restrict__ eps, int total4) {
    int i = blockIdx.x * blockDim.x + threadIdx.x;
    if (blockIdx.x == 0 && threadIdx.x < DIM) {
        g_sum[threadIdx.x] = 0.f;
        g_sq[threadIdx.x] = 0.f;
    }
    if (i < total4) {
        float e = 1.0f + eps[0];
        float4 v = ((const float4*)h)[i];
        v.x *= e; v.y *= e; v.z *= e; v.w *= e;
        ((float4*)g_z)[i] = v;
    }
}

// ---------------------------------------------------------------------------
// 2) z[dst] += h[src]  — warp per edge, lane covers 16B, ONE vector reduction
//    (red.global.add.v4.f32, PTX ISA 8.1 / sm_90+) instead of 4 scalar RED.32.
// ---------------------------------------------------------------------------
__global__ void edge_kernel(const float* __restrict__ h,
                            const int* __restrict__ src,
                            const int* __restrict__ dst,
                            int nnodes, long long total) {
    long long idx = (long long)blockIdx.x * blockDim.x + threadIdx.x;
    if (idx >= total) return;
    long long e = idx >> 5;
    int lane = (int)(idx & 31);
    int s = src[e];   // broadcast across warp (same address)
    int d = dst[e];
    if ((unsigned)s >= (unsigned)nnodes || (unsigned)d >= (unsigned)nnodes) return;
    float4 v = *(const float4*)(h + (long long)s * DIM + lane * 4);
    float* p = g_z + (long long)d * DIM + lane * 4;
    asm volatile("red.global.add.v4.f32 [%0], {%1, %2, %3, %4};"
                 :: "l"(p), "f"(v.x), "f"(v.y), "f"(v.z), "f"(v.w)
                 : "memory");
}

// ---------------------------------------------------------------------------
// 3/4) C = act(A @ W + b).  64-row x 128-col tile per block, K=128 in smem.
// ---------------------------------------------------------------------------
__global__ __launch_bounds__(256, 2)
void gemm_kernel(const float* __restrict__ A, const float* __restrict__ W,
                 const float* __restrict__ bias, float* __restrict__ C,
                 int M, int do_relu) {
    extern __shared__ float sm[];
    float* Ws = sm;              // DIM*DIM floats   (64 KB)
    float* As = sm + DIM * DIM;  // 64*DIM floats    (32 KB)
    int tid = threadIdx.x;
    int row0 = blockIdx.x * 64;

    const float4* W4 = (const float4*)W;
    float4* Ws4 = (float4*)Ws;
#pragma unroll
    for (int i = 0; i < 16; i++) Ws4[tid + 256 * i] = W4[tid + 256 * i];

    float4* As4 = (float4*)As;
#pragma unroll
    for (int i = 0; i < 8; i++) {
        int idx = tid + 256 * i;
        int r = idx >> 5;
        int c = idx & 31;
        float4 v = make_float4(0.f, 0.f, 0.f, 0.f);
        int gr = row0 + r;
        if (gr < M) v = ((const float4*)A)[(long long)gr * 32 + c];
        As4[idx] = v;
    }
    __syncthreads();

    int cg = tid & 31;   // column group -> cols [4cg, 4cg+4)
    int rg = tid >> 5;   // row group    -> rows [rg*8, rg*8+8)

    float acc[8][4];
#pragma unroll
    for (int i = 0; i < 8; i++) {
        acc[i][0] = 0.f; acc[i][1] = 0.f; acc[i][2] = 0.f; acc[i][3] = 0.f;
    }

    const float* Ar = As + rg * 8 * DIM;
#pragma unroll 4
    for (int k = 0; k < DIM; k += 4) {
        float4 w0 = *(const float4*)(Ws + (k + 0) * DIM + cg * 4);
        float4 w1 = *(const float4*)(Ws + (k + 1) * DIM + cg * 4);
        float4 w2 = *(const float4*)(Ws + (k + 2) * DIM + cg * 4);
        float4 w3 = *(const float4*)(Ws + (k + 3) * DIM + cg * 4);
#pragma unroll
        for (int i = 0; i < 8; i++) {
            float4 a = *(const float4*)(Ar + i * DIM + k);  // warp-broadcast
            acc[i][0] += a.x * w0.x + a.y * w1.x + a.z * w2.x + a.w * w3.x;
            acc[i][1] += a.x * w0.y + a.y * w1.y + a.z * w2.y + a.w * w3.y;
            acc[i][2] += a.x * w0.z + a.y * w1.z + a.z * w2.z + a.w * w3.z;
            acc[i][3] += a.x * w0.w + a.y * w1.w + a.z * w2.w + a.w * w3.w;
        }
    }

    float4 b4 = ((const float4*)bias)[cg];
#pragma unroll
    for (int i = 0; i < 8; i++) {
        int gr = row0 + rg * 8 + i;
        if (gr < M) {
            float4 o;
            o.x = acc[i][0] + b4.x;
            o.y = acc[i][1] + b4.y;
            o.z = acc[i][2] + b4.z;
            o.w = acc[i][3] + b4.w;
            if (do_relu) {
                o.x = fmaxf(o.x, 0.f); o.y = fmaxf(o.y, 0.f);
                o.z = fmaxf(o.z, 0.f); o.w = fmaxf(o.w, 0.f);
            }
            ((float4*)(C + (long long)gr * DIM))[cg] = o;
        }
    }
}

// ---------------------------------------------------------------------------
// 5) BN stats: per-column sum & sumsq (coalesced; one atomic per block/column)
// ---------------------------------------------------------------------------
#define STAT_ROWS 512
__global__ void stats_kernel(const float* __restrict__ Z, int M) {
    int col = threadIdx.x;  // 128 threads
    int r0 = blockIdx.x * STAT_ROWS;
    int r1 = min(r0 + STAT_ROWS, M);
    float s = 0.f, q = 0.f;
    for (int r = r0; r < r1; r++) {
        float v = Z[(long long)r * DIM + col];
        s += v;
        q += v * v;
    }
    atomicAdd(&g_sum[col], s);
    atomicAdd(&g_sq[col], q);
}

// ---------------------------------------------------------------------------
// 6) fold BN stats into per-column scale/shift
// ---------------------------------------------------------------------------
__global__ void bnfin_kernel(const float* __restrict__ gamma,
                             const float* __restrict__ beta, float invN) {
    int t = threadIdx.x;
    float mean = g_sum[t] * invN;
    float var = g_sq[t] * invN - mean * mean;
    float sc = gamma[t] * rsqrtf(var + 1e-5f);
    g_scale[t] = sc;
    g_shift[t] = beta[t] - mean * sc;
}

// ---------------------------------------------------------------------------
// 7) out = h + leaky_relu(z*scale + shift)
// ---------------------------------------------------------------------------
__global__ void ewise_kernel(const float* __restrict__ h,
                             const float* __restrict__ Z,
                             float* __restrict__ out, int total4) {
    int i = blockIdx.x * blockDim.x + threadIdx.x;
    if (i >= total4) return;
    int cg = i & 31;
    float4 sc = ((const float4*)g_scale)[cg];
    float4 sh = ((const float4*)g_shift)[cg];
    float4 zv = ((const float4*)Z)[i];
    float4 hv = ((const float4*)h)[i];
    float x;
    float4 o;
    x = zv.x * sc.x + sh.x; o.x = hv.x + (x >= 0.f ? x : 0.01f * x);
    x = zv.y * sc.y + sh.y; o.y = hv.y + (x >= 0.f ? x : 0.01f * x);
    x = zv.z * sc.z + sh.z; o.z = hv.z + (x >= 0.f ? x : 0.01f * x);
    x = zv.w * sc.w + sh.w; o.w = hv.w + (x >= 0.f ? x : 0.01f * x);
    ((float4*)out)[i] = o;
}

// ---------------------------------------------------------------------------
extern "C" void kernel_launch(void* const* d_in, const int* in_sizes, int n_in,
                              void* d_out, int out_size) {
    const float* h     = (const float*)d_in[0];
    const int*   src   = (const int*)d_in[1];
    const int*   dst   = (const int*)d_in[2];
    const float* eps   = (const float*)d_in[3];
    const float* W1    = (const float*)d_in[4];
    const float* b1    = (const float*)d_in[5];
    const float* W2    = (const float*)d_in[6];
    const float* b2    = (const float*)d_in[7];
    const float* gamma = (const float*)d_in[8];
    const float* beta  = (const float*)d_in[9];
    float* out = (float*)d_out;

    int N = in_sizes[0] / DIM;
    long long E = in_sizes[1];
    int total4 = N * (DIM / 4);

    size_t smem = (size_t)(DIM * DIM + 64 * DIM) * sizeof(float);  // 96 KB
    cudaFuncSetAttribute(gemm_kernel,
                         cudaFuncAttributeMaxDynamicSharedMemorySize,
                         (int)smem);

    void *zp = nullptr, *yp = nullptr;
    cudaGetSymbolAddress(&zp, g_z);
    cudaGetSymbolAddress(&yp, g_y);

    // 1) z = (1+eps)*h ; zero stats
    init_kernel<<<(total4 + 255) / 256, 256>>>(h, eps, total4);

    // 2) scatter-add edges (vector RED.128)
    long long tot = E * 32;
    edge_kernel<<<(int)((tot + 255) / 256), 256>>>(h, src, dst, N, tot);

    // 3) y = relu(z @ W1 + b1)
    int gblocks = (N + 63) / 64;
    gemm_kernel<<<gblocks, 256, smem>>>((const float*)zp, W1, b1, (float*)yp, N, 1);

    // 4) z = y @ W2 + b2
    gemm_kernel<<<gblocks, 256, smem>>>((const float*)yp, W2, b2, (float*)zp, N, 0);

    // 5) BN column stats
    stats_kernel<<<(N + STAT_ROWS - 1) / STAT_ROWS, DIM>>>((const float*)zp, N);

    // 6) fold into scale/shift
    bnfin_kernel<<<1, DIM>>>(gamma, beta, 1.0f / (float)N);

    // 7) out = h + leaky(z*scale + shift)
    ewise_kernel<<<(total4 + 255) / 256, 256>>>(h, (const float*)zp, out, total4);
}

// round 4
// speedup vs baseline: 2.6327x; 1.4852x over previous
#include <cuda_runtime.h>

#define DIM 128
#define NODES_MAX 50304
#define EDGES_MAX 1700000
#define SCAN_B 1024
#define SCAN_NBLK ((NODES_MAX + SCAN_B - 1) / SCAN_B)

// Scratch (static device globals — no runtime allocation allowed)
__device__ __align__(16) float g_z[NODES_MAX * DIM];
__device__ __align__(16) float g_y[NODES_MAX * DIM];
__device__ float g_sum[DIM];
__device__ float g_sq[DIM];
__device__ float g_scale[DIM];
__device__ float g_shift[DIM];
__device__ int g_deg[NODES_MAX];
__device__ int g_off[NODES_MAX];
__device__ int g_cur[NODES_MAX];
__device__ int g_bsum[SCAN_NBLK];
__device__ int g_elist[EDGES_MAX];

// ---------------------------------------------------------------------------
// 0) zero degree counters + BN stat accumulators
// ---------------------------------------------------------------------------
__global__ void zero_kernel(int n) {
    int i = blockIdx.x * blockDim.x + threadIdx.x;
    if (i < n) g_deg[i] = 0;
    if (i < DIM) { g_sum[i] = 0.f; g_sq[i] = 0.f; }
}

// ---------------------------------------------------------------------------
// 1) degree histogram over dst
// ---------------------------------------------------------------------------
__global__ void count_kernel(const int* __restrict__ dst, int nnodes, int E) {
    int e = blockIdx.x * blockDim.x + threadIdx.x;
    if (e >= E) return;
    int d = dst[e];
    if ((unsigned)d < (unsigned)nnodes) atomicAdd(&g_deg[d], 1);
}

// ---------------------------------------------------------------------------
// 2a) per-block degree sums
// ---------------------------------------------------------------------------
__global__ void scan_reduce_kernel(int n) {
    __shared__ int sm[SCAN_B];
    int t = threadIdx.x;
    int i = blockIdx.x * SCAN_B + t;
    sm[t] = (i < n) ? g_deg[i] : 0;
    __syncthreads();
    for (int s = SCAN_B / 2; s > 0; s >>= 1) {
        if (t < s) sm[t] += sm[t + s];
        __syncthreads();
    }
    if (t == 0) g_bsum[blockIdx.x] = sm[0];
}

// 2b) exclusive scan of block sums (single block)
__global__ void scan_top_kernel(int nblk) {
    __shared__ int sm[SCAN_NBLK + 1];
    int t = threadIdx.x;
    if (t == 0) {
        int run = 0;
        for (int b = 0; b < nblk; b++) { sm[b] = run; run += g_bsum[b]; }
    }
    __syncthreads();
    if (t < nblk) g_bsum[t] = sm[t];
}

// 2c) block-local exclusive scan + block prefix -> offsets & cursors
__global__ void scan_final_kernel(int n) {
    __shared__ int sm[SCAN_B];
    int t = threadIdx.x;
    int i = blockIdx.x * SCAN_B + t;
    int d = (i < n) ? g_deg[i] : 0;
    sm[t] = d;
    __syncthreads();
    // Hillis-Steele inclusive scan
    for (int s = 1; s < SCAN_B; s <<= 1) {
        int v = (t >= s) ? sm[t - s] : 0;
        __syncthreads();
        sm[t] += v;
        __syncthreads();
    }
    if (i < n) {
        int excl = sm[t] - d + g_bsum[blockIdx.x];
        g_off[i] = excl;
        g_cur[i] = excl;
    }
}

// ---------------------------------------------------------------------------
// 3) scatter src ids into per-dst segments
// ---------------------------------------------------------------------------
__global__ void scatter_kernel(const int* __restrict__ src,
                               const int* __restrict__ dst, int nnodes, int E) {
    int e = blockIdx.x * blockDim.x + threadIdx.x;
    if (e >= E) return;
    int d = dst[e];
    int s = src[e];
    if ((unsigned)d >= (unsigned)nnodes || (unsigned)s >= (unsigned)nnodes) return;
    int pos = atomicAdd(&g_cur[d], 1);
    g_elist[pos] = s;
}

// ---------------------------------------------------------------------------
// 4) gather: z[u] = (1+eps)*h[u] + sum_{v in elist[u]} h[v]
//    warp per node; lane covers 4 feats; neighbor ids via shfl broadcast.
// ---------------------------------------------------------------------------
__global__ void gather_kernel(const float* __restrict__ h,
                              const float* __restrict__ eps, int nnodes) {
    int warp = (blockIdx.x * blockDim.x + threadIdx.x) >> 5;
    int lane = threadIdx.x & 31;
    if (warp >= nnodes) return;
    int u = warp;
    int off = g_off[u];
    int dg = g_deg[u];

    float4 acc = make_float4(0.f, 0.f, 0.f, 0.f);
    int j = 0;
    for (; j + 32 <= dg; j += 32) {
        int vid = g_elist[off + j + lane];
#pragma unroll
        for (int k = 0; k < 32; k++) {
            int v = __shfl_sync(0xffffffffu, vid, k);
            float4 x = *(const float4*)(h + (long long)v * DIM + lane * 4);
            acc.x += x.x; acc.y += x.y; acc.z += x.z; acc.w += x.w;
        }
    }
    int rem = dg - j;
    if (rem > 0) {
        int vid = (lane < rem) ? g_elist[off + j + lane] : 0;
        for (int k = 0; k < rem; k++) {
            int v = __shfl_sync(0xffffffffu, vid, k);
            float4 x = *(const float4*)(h + (long long)v * DIM + lane * 4);
            acc.x += x.x; acc.y += x.y; acc.z += x.z; acc.w += x.w;
        }
    }
    float e = 1.0f + eps[0];
    float4 hv = *(const float4*)(h + (long long)u * DIM + lane * 4);
    acc.x += e * hv.x; acc.y += e * hv.y; acc.z += e * hv.z; acc.w += e * hv.w;
    *(float4*)(g_z + (long long)u * DIM + lane * 4) = acc;
}

// ---------------------------------------------------------------------------
// 5/6) C = act(A @ W + b); optionally accumulate BN column stats of C.
// ---------------------------------------------------------------------------
__global__ __launch_bounds__(256, 2)
void gemm_kernel(const float* __restrict__ A, const float* __restrict__ W,
                 const float* __restrict__ bias, float* __restrict__ C,
                 int M, int do_relu, int do_stats) {
    extern __shared__ float sm[];
    float* Ws = sm;              // DIM*DIM floats   (64 KB)
    float* As = sm + DIM * DIM;  // 64*DIM floats    (32 KB)
    int tid = threadIdx.x;
    int row0 = blockIdx.x * 64;

    const float4* W4 = (const float4*)W;
    float4* Ws4 = (float4*)Ws;
#pragma unroll
    for (int i = 0; i < 16; i++) Ws4[tid + 256 * i] = W4[tid + 256 * i];

    float4* As4 = (float4*)As;
#pragma unroll
    for (int i = 0; i < 8; i++) {
        int idx = tid + 256 * i;
        int r = idx >> 5;
        int c = idx & 31;
        float4 v = make_float4(0.f, 0.f, 0.f, 0.f);
        int gr = row0 + r;
        if (gr < M) v = ((const float4*)A)[(long long)gr * 32 + c];
        As4[idx] = v;
    }
    __syncthreads();

    int cg = tid & 31;   // column group -> cols [4cg, 4cg+4)
    int rg = tid >> 5;   // row group    -> rows [rg*8, rg*8+8)

    float acc[8][4];
#pragma unroll
    for (int i = 0; i < 8; i++) {
        acc[i][0] = 0.f; acc[i][1] = 0.f; acc[i][2] = 0.f; acc[i][3] = 0.f;
    }

    const float* Ar = As + rg * 8 * DIM;
#pragma unroll 4
    for (int k = 0; k < DIM; k += 4) {
        float4 w0 = *(const float4*)(Ws + (k + 0) * DIM + cg * 4);
        float4 w1 = *(const float4*)(Ws + (k + 1) * DIM + cg * 4);
        float4 w2 = *(const float4*)(Ws + (k + 2) * DIM + cg * 4);
        float4 w3 = *(const float4*)(Ws + (k + 3) * DIM + cg * 4);
#pragma unroll
        for (int i = 0; i < 8; i++) {
            float4 a = *(const float4*)(Ar + i * DIM + k);  // warp-broadcast
            acc[i][0] += a.x * w0.x + a.y * w1.x + a.z * w2.x + a.w * w3.x;
            acc[i][1] += a.x * w0.y + a.y * w1.y + a.z * w2.y + a.w * w3.y;
            acc[i][2] += a.x * w0.z + a.y * w1.z + a.z * w2.z + a.w * w3.z;
            acc[i][3] += a.x * w0.w + a.y * w1.w + a.z * w2.w + a.w * w3.w;
        }
    }

    float4 b4 = ((const float4*)bias)[cg];
    float s4[4] = {0.f, 0.f, 0.f, 0.f};
    float q4[4] = {0.f, 0.f, 0.f, 0.f};
#pragma unroll
    for (int i = 0; i < 8; i++) {
        int gr = row0 + rg * 8 + i;
        if (gr < M) {
            float4 o;
            o.x = acc[i][0] + b4.x;
            o.y = acc[i][1] + b4.y;
            o.z = acc[i][2] + b4.z;
            o.w = acc[i][3] + b4.w;
            if (do_relu) {
                o.x = fmaxf(o.x, 0.f); o.y = fmaxf(o.y, 0.f);
                o.z = fmaxf(o.z, 0.f); o.w = fmaxf(o.w, 0.f);
            }
            s4[0] += o.x; s4[1] += o.y; s4[2] += o.z; s4[3] += o.w;
            q4[0] += o.x * o.x; q4[1] += o.y * o.y;
            q4[2] += o.z * o.z; q4[3] += o.w * o.w;
            ((float4*)(C + (long long)gr * DIM))[cg] = o;
        }
    }

    if (do_stats) {
        // reduce per-column partials across the 8 row-groups via smem
        __syncthreads();  // done reading As
        float* Ss = As;          // [128 cols][8 rg]
        float* Qs = As + 1024;   // [128 cols][8 rg]
#pragma unroll
        for (int c = 0; c < 4; c++) {
            Ss[(cg * 4 + c) * 8 + rg] = s4[c];
            Qs[(cg * 4 + c) * 8 + rg] = q4[c];
        }
        __syncthreads();
        if (tid < DIM) {
            float s = 0.f, q = 0.f;
#pragma unroll
            for (int r = 0; r < 8; r++) {
                s += Ss[tid * 8 + r];
                q += Qs[tid * 8 + r];
            }
            atomicAdd(&g_sum[tid], s);
            atomicAdd(&g_sq[tid], q);
        }
    }
}

// ---------------------------------------------------------------------------
// 7) fold BN stats into per-column scale/shift
// ---------------------------------------------------------------------------
__global__ void bnfin_kernel(const float* __restrict__ gamma,
                             const float* __restrict__ beta, float invN) {
    int t = threadIdx.x;
    float mean = g_sum[t] * invN;
    float var = g_sq[t] * invN - mean * mean;
    float sc = gamma[t] * rsqrtf(var + 1e-5f);
    g_scale[t] = sc;
    g_shift[t] = beta[t] - mean * sc;
}

// ---------------------------------------------------------------------------
// 8) out = h + leaky_relu(z*scale + shift)
// ---------------------------------------------------------------------------
__global__ void ewise_kernel(const float* __restrict__ h,
                             const float* __restrict__ Z,
                             float* __restrict__ out, int total4) {
    int i = blockIdx.x * blockDim.x + threadIdx.x;
    if (i >= total4) return;
    int cg = i & 31;
    float4 sc = ((const float4*)g_scale)[cg];
    float4 sh = ((const float4*)g_shift)[cg];
    float4 zv = ((const float4*)Z)[i];
    float4 hv = ((const float4*)h)[i];
    float x;
    float4 o;
    x = zv.x * sc.x + sh.x; o.x = hv.x + (x >= 0.f ? x : 0.01f * x);
    x = zv.y * sc.y + sh.y; o.y = hv.y + (x >= 0.f ? x : 0.01f * x);
    x = zv.z * sc.z + sh.z; o.z = hv.z + (x >= 0.f ? x : 0.01f * x);
    x = zv.w * sc.w + sh.w; o.w = hv.w + (x >= 0.f ? x : 0.01f * x);
    ((float4*)out)[i] = o;
}

// ---------------------------------------------------------------------------
extern "C" void kernel_launch(void* const* d_in, const int* in_sizes, int n_in,
                              void* d_out, int out_size) {
    const float* h     = (const float*)d_in[0];
    const int*   src   = (const int*)d_in[1];
    const int*   dst   = (const int*)d_in[2];
    const float* eps   = (const float*)d_in[3];
    const float* W1    = (const float*)d_in[4];
    const float* b1    = (const float*)d_in[5];
    const float* W2    = (const float*)d_in[6];
    const float* b2    = (const float*)d_in[7];
    const float* gamma = (const float*)d_in[8];
    const float* beta  = (const float*)d_in[9];
    float* out = (float*)d_out;

    int N = in_sizes[0] / DIM;
    int E = in_sizes[1];
    int total4 = N * (DIM / 4);
    int nblk = (N + SCAN_B - 1) / SCAN_B;

    size_t smem = (size_t)(DIM * DIM + 64 * DIM) * sizeof(float);  // 96 KB
    cudaFuncSetAttribute(gemm_kernel,
                         cudaFuncAttributeMaxDynamicSharedMemorySize,
                         (int)smem);

    void *zp = nullptr, *yp = nullptr;
    cudaGetSymbolAddress(&zp, g_z);
    cudaGetSymbolAddress(&yp, g_y);

    // 0-3) build CSR of incoming edges
    zero_kernel<<<(N + 255) / 256, 256>>>(N);
    count_kernel<<<(E + 255) / 256, 256>>>(dst, N, E);
    scan_reduce_kernel<<<nblk, SCAN_B>>>(N);
    scan_top_kernel<<<1, SCAN_NBLK>>>(nblk);
    scan_final_kernel<<<nblk, SCAN_B>>>(N);
    scatter_kernel<<<(E + 255) / 256, 256>>>(src, dst, N, E);

    // 4) gather + (1+eps)*h fused
    gather_kernel<<<(N * 32 + 255) / 256, 256>>>(h, eps, N);

    // 5) y = relu(z @ W1 + b1)
    int gblocks = (N + 63) / 64;
    gemm_kernel<<<gblocks, 256, smem>>>((const float*)zp, W1, b1, (float*)yp, N, 1, 0);

    // 6) z = y @ W2 + b2  (+ BN stats fused)
    gemm_kernel<<<gblocks, 256, smem>>>((const float*)yp, W2, b2, (float*)zp, N, 0, 1);

    // 7) fold into scale/shift
    bnfin_kernel<<<1, DIM>>>(gamma, beta, 1.0f / (float)N);

    // 8) out = h + leaky(z*scale + shift)
    ewise_kernel<<<(total4 + 255) / 256, 256>>>(h, (const float*)zp, out, total4);
}

// round 5
// speedup vs baseline: 2.7996x; 1.0634x over previous
#include <cuda_runtime.h>

#define DIM 128
#define NODES_MAX 50304
#define EDGES_MAX 1700000
#define SCAN_B 1024
#define SCAN_NBLK ((NODES_MAX + SCAN_B - 1) / SCAN_B)

typedef unsigned long long ull;

// Scratch (static device globals — no runtime allocation allowed)
__device__ __align__(16) float g_z[NODES_MAX * DIM];
__device__ __align__(16) float g_y[NODES_MAX * DIM];
__device__ float g_sum[DIM];
__device__ float g_sq[DIM];
__device__ float g_scale[DIM];
__device__ float g_shift[DIM];
__device__ int g_deg[NODES_MAX];
__device__ int g_off[NODES_MAX];
__device__ int g_cur[NODES_MAX];
__device__ int g_bsum[SCAN_NBLK];
__device__ int g_elist[EDGES_MAX];

// ---- packed f32x2 helpers (sm_103a FFMA2) ---------------------------------
__device__ __forceinline__ void fma2(ull& acc, ull a, ull b) {
    asm("fma.rn.f32x2 %0, %1, %2, %0;" : "+l"(acc) : "l"(a), "l"(b));
}
__device__ __forceinline__ ull pack2(float x) {
    ull r;
    asm("mov.b64 %0, {%1, %1};" : "=l"(r) : "f"(x));
    return r;
}
__device__ __forceinline__ void unpack2(ull v, float& lo, float& hi) {
    asm("mov.b64 {%0, %1}, %2;" : "=f"(lo), "=f"(hi) : "l"(v));
}

// ---------------------------------------------------------------------------
// 0) zero degree counters + BN stat accumulators
// ---------------------------------------------------------------------------
__global__ void zero_kernel(int n) {
    int i = blockIdx.x * blockDim.x + threadIdx.x;
    if (i < n) g_deg[i] = 0;
    if (i < DIM) { g_sum[i] = 0.f; g_sq[i] = 0.f; }
}

// ---------------------------------------------------------------------------
// 1) degree histogram over dst
// ---------------------------------------------------------------------------
__global__ void count_kernel(const int* __restrict__ dst, int nnodes, int E) {
    int e = blockIdx.x * blockDim.x + threadIdx.x;
    if (e >= E) return;
    int d = dst[e];
    if ((unsigned)d < (unsigned)nnodes) atomicAdd(&g_deg[d], 1);
}

// ---------------------------------------------------------------------------
// 2a) per-block degree sums
// ---------------------------------------------------------------------------
__global__ void scan_reduce_kernel(int n) {
    __shared__ int sm[SCAN_B];
    int t = threadIdx.x;
    int i = blockIdx.x * SCAN_B + t;
    sm[t] = (i < n) ? g_deg[i] : 0;
    __syncthreads();
    for (int s = SCAN_B / 2; s > 0; s >>= 1) {
        if (t < s) sm[t] += sm[t + s];
        __syncthreads();
    }
    if (t == 0) g_bsum[blockIdx.x] = sm[0];
}

// 2b) exclusive scan of block sums (parallel, 64 threads)
__global__ void scan_top_kernel(int nblk) {
    __shared__ int sm[64];
    int t = threadIdx.x;
    int v = (t < nblk) ? g_bsum[t] : 0;
    sm[t] = v;
    __syncthreads();
    for (int s = 1; s < 64; s <<= 1) {
        int x = (t >= s) ? sm[t - s] : 0;
        __syncthreads();
        sm[t] += x;
        __syncthreads();
    }
    if (t < nblk) g_bsum[t] = sm[t] - v;  // exclusive
}

// 2c) block-local exclusive scan + block prefix -> offsets & cursors
__global__ void scan_final_kernel(int n) {
    __shared__ int sm[SCAN_B];
    int t = threadIdx.x;
    int i = blockIdx.x * SCAN_B + t;
    int d = (i < n) ? g_deg[i] : 0;
    sm[t] = d;
    __syncthreads();
    for (int s = 1; s < SCAN_B; s <<= 1) {
        int v = (t >= s) ? sm[t - s] : 0;
        __syncthreads();
        sm[t] += v;
        __syncthreads();
    }
    if (i < n) {
        int excl = sm[t] - d + g_bsum[blockIdx.x];
        g_off[i] = excl;
        g_cur[i] = excl;
    }
}

// ---------------------------------------------------------------------------
// 3) scatter src ids into per-dst segments
// ---------------------------------------------------------------------------
__global__ void scatter_kernel(const int* __restrict__ src,
                               const int* __restrict__ dst, int nnodes, int E) {
    int e = blockIdx.x * blockDim.x + threadIdx.x;
    if (e >= E) return;
    int d = dst[e];
    int s = src[e];
    if ((unsigned)d >= (unsigned)nnodes || (unsigned)s >= (unsigned)nnodes) return;
    int pos = atomicAdd(&g_cur[d], 1);
    g_elist[pos] = s;
}

// ---------------------------------------------------------------------------
// 4) gather: z[u] = (1+eps)*h[u] + sum_{v in elist[u]} h[v]
// ---------------------------------------------------------------------------
__global__ void gather_kernel(const float* __restrict__ h,
                              const float* __restrict__ eps, int nnodes) {
    int warp = (blockIdx.x * blockDim.x + threadIdx.x) >> 5;
    int lane = threadIdx.x & 31;
    if (warp >= nnodes) return;
    int u = warp;
    int off = g_off[u];
    int dg = g_deg[u];

    float4 acc = make_float4(0.f, 0.f, 0.f, 0.f);
    int j = 0;
    for (; j + 32 <= dg; j += 32) {
        int vid = g_elist[off + j + lane];
#pragma unroll
        for (int k = 0; k < 32; k++) {
            int v = __shfl_sync(0xffffffffu, vid, k);
            float4 x = *(const float4*)(h + (long long)v * DIM + lane * 4);
            acc.x += x.x; acc.y += x.y; acc.z += x.z; acc.w += x.w;
        }
    }
    int rem = dg - j;
    if (rem > 0) {
        int vid = (lane < rem) ? g_elist[off + j + lane] : 0;
        for (int k = 0; k < rem; k++) {
            int v = __shfl_sync(0xffffffffu, vid, k);
            float4 x = *(const float4*)(h + (long long)v * DIM + lane * 4);
            acc.x += x.x; acc.y += x.y; acc.z += x.z; acc.w += x.w;
        }
    }
    float e = 1.0f + eps[0];
    float4 hv = *(const float4*)(h + (long long)u * DIM + lane * 4);
    acc.x += e * hv.x; acc.y += e * hv.y; acc.z += e * hv.z; acc.w += e * hv.w;
    *(float4*)(g_z + (long long)u * DIM + lane * 4) = acc;
}

// ---------------------------------------------------------------------------
// 5/6) C = act(A @ W + b) with packed f32x2 FMA; optional BN stats of C.
// ---------------------------------------------------------------------------
__global__ __launch_bounds__(256, 2)
void gemm_kernel(const float* __restrict__ A, const float* __restrict__ W,
                 const float* __restrict__ bias, float* __restrict__ C,
                 int M, int do_relu, int do_stats) {
    extern __shared__ float sm[];
    float* Ws = sm;              // DIM*DIM floats   (64 KB)
    float* As = sm + DIM * DIM;  // 64*DIM floats    (32 KB)
    int tid = threadIdx.x;
    int row0 = blockIdx.x * 64;

    const float4* W4 = (const float4*)W;
    float4* Ws4 = (float4*)Ws;
#pragma unroll
    for (int i = 0; i < 16; i++) Ws4[tid + 256 * i] = W4[tid + 256 * i];

    float4* As4 = (float4*)As;
#pragma unroll
    for (int i = 0; i < 8; i++) {
        int idx = tid + 256 * i;
        int r = idx >> 5;
        int c = idx & 31;
        float4 v = make_float4(0.f, 0.f, 0.f, 0.f);
        int gr = row0 + r;
        if (gr < M) v = ((const float4*)A)[(long long)gr * 32 + c];
        As4[idx] = v;
    }
    __syncthreads();

    int cg = tid & 31;   // column group -> cols [4cg, 4cg+4)
    int rg = tid >> 5;   // row group    -> rows [rg*8, rg*8+8)

    // acc2[i][0] holds cols {4cg, 4cg+1}; acc2[i][1] holds cols {4cg+2, 4cg+3}
    ull acc2[8][2];
#pragma unroll
    for (int i = 0; i < 8; i++) { acc2[i][0] = 0ull; acc2[i][1] = 0ull; }

    const float* Ar = As + rg * 8 * DIM;
#pragma unroll 4
    for (int k = 0; k < DIM; k += 4) {
        // LDS.128 reads land adjacent column pairs directly in 64-bit regs
        double2 w0 = *(const double2*)(Ws + (k + 0) * DIM + cg * 4);
        double2 w1 = *(const double2*)(Ws + (k + 1) * DIM + cg * 4);
        double2 w2 = *(const double2*)(Ws + (k + 2) * DIM + cg * 4);
        double2 w3 = *(const double2*)(Ws + (k + 3) * DIM + cg * 4);
        ull w0l = __double_as_longlong(w0.x), w0h = __double_as_longlong(w0.y);
        ull w1l = __double_as_longlong(w1.x), w1h = __double_as_longlong(w1.y);
        ull w2l = __double_as_longlong(w2.x), w2h = __double_as_longlong(w2.y);
        ull w3l = __double_as_longlong(w3.x), w3h = __double_as_longlong(w3.y);
#pragma unroll
        for (int i = 0; i < 8; i++) {
            float4 a = *(const float4*)(Ar + i * DIM + k);  // warp-broadcast
            ull ax = pack2(a.x), ay = pack2(a.y), az = pack2(a.z), aw = pack2(a.w);
            fma2(acc2[i][0], ax, w0l); fma2(acc2[i][1], ax, w0h);
            fma2(acc2[i][0], ay, w1l); fma2(acc2[i][1], ay, w1h);
            fma2(acc2[i][0], az, w2l); fma2(acc2[i][1], az, w2h);
            fma2(acc2[i][0], aw, w3l); fma2(acc2[i][1], aw, w3h);
        }
    }

    float4 b4 = ((const float4*)bias)[cg];
    float s4[4] = {0.f, 0.f, 0.f, 0.f};
    float q4[4] = {0.f, 0.f, 0.f, 0.f};
#pragma unroll
    for (int i = 0; i < 8; i++) {
        int gr = row0 + rg * 8 + i;
        if (gr < M) {
            float4 o;
            unpack2(acc2[i][0], o.x, o.y);
            unpack2(acc2[i][1], o.z, o.w);
            o.x += b4.x; o.y += b4.y; o.z += b4.z; o.w += b4.w;
            if (do_relu) {
                o.x = fmaxf(o.x, 0.f); o.y = fmaxf(o.y, 0.f);
                o.z = fmaxf(o.z, 0.f); o.w = fmaxf(o.w, 0.f);
            }
            s4[0] += o.x; s4[1] += o.y; s4[2] += o.z; s4[3] += o.w;
            q4[0] += o.x * o.x; q4[1] += o.y * o.y;
            q4[2] += o.z * o.z; q4[3] += o.w * o.w;
            ((float4*)(C + (long long)gr * DIM))[cg] = o;
        }
    }

    if (do_stats) {
        __syncthreads();  // done reading As
        float* Ss = As;          // [128 cols][8 rg]
        float* Qs = As + 1024;   // [128 cols][8 rg]
#pragma unroll
        for (int c = 0; c < 4; c++) {
            Ss[(cg * 4 + c) * 8 + rg] = s4[c];
            Qs[(cg * 4 + c) * 8 + rg] = q4[c];
        }
        __syncthreads();
        if (tid < DIM) {
            float s = 0.f, q = 0.f;
#pragma unroll
            for (int r = 0; r < 8; r++) {
                s += Ss[tid * 8 + r];
                q += Qs[tid * 8 + r];
            }
            atomicAdd(&g_sum[tid], s);
            atomicAdd(&g_sq[tid], q);
        }
    }
}

// ---------------------------------------------------------------------------
// 7) fold BN stats into per-column scale/shift
// ---------------------------------------------------------------------------
__global__ void bnfin_kernel(const float* __restrict__ gamma,
                             const float* __restrict__ beta, float invN) {
    int t = threadIdx.x;
    float mean = g_sum[t] * invN;
    float var = g_sq[t] * invN - mean * mean;
    float sc = gamma[t] * rsqrtf(var + 1e-5f);
    g_scale[t] = sc;
    g_shift[t] = beta[t] - mean * sc;
}

// ---------------------------------------------------------------------------
// 8) out = h + leaky_relu(z*scale + shift)
// ---------------------------------------------------------------------------
__global__ void ewise_kernel(const float* __restrict__ h,
                             const float* __restrict__ Z,
                             float* __restrict__ out, int total4) {
    int i = blockIdx.x * blockDim.x + threadIdx.x;
    if (i >= total4) return;
    int cg = i & 31;
    float4 sc = ((const float4*)g_scale)[cg];
    float4 sh = ((const float4*)g_shift)[cg];
    float4 zv = ((const float4*)Z)[i];
    float4 hv = ((const float4*)h)[i];
    float x;
    float4 o;
    x = zv.x * sc.x + sh.x; o.x = hv.x + (x >= 0.f ? x : 0.01f * x);
    x = zv.y * sc.y + sh.y; o.y = hv.y + (x >= 0.f ? x : 0.01f * x);
    x = zv.z * sc.z + sh.z; o.z = hv.z + (x >= 0.f ? x : 0.01f * x);
    x = zv.w * sc.w + sh.w; o.w = hv.w + (x >= 0.f ? x : 0.01f * x);
    ((float4*)out)[i] = o;
}

// ---------------------------------------------------------------------------
extern "C" void kernel_launch(void* const* d_in, const int* in_sizes, int n_in,
                              void* d_out, int out_size) {
    const float* h     = (const float*)d_in[0];
    const int*   src   = (const int*)d_in[1];
    const int*   dst   = (const int*)d_in[2];
    const float* eps   = (const float*)d_in[3];
    const float* W1    = (const float*)d_in[4];
    const float* b1    = (const float*)d_in[5];
    const float* W2    = (const float*)d_in[6];
    const float* b2    = (const float*)d_in[7];
    const float* gamma = (const float*)d_in[8];
    const float* beta  = (const float*)d_in[9];
    float* out = (float*)d_out;

    int N = in_sizes[0] / DIM;
    int E = in_sizes[1];
    int total4 = N * (DIM / 4);
    int nblk = (N + SCAN_B - 1) / SCAN_B;

    size_t smem = (size_t)(DIM * DIM + 64 * DIM) * sizeof(float);  // 96 KB
    cudaFuncSetAttribute(gemm_kernel,
                         cudaFuncAttributeMaxDynamicSharedMemorySize,
                         (int)smem);

    void *zp = nullptr, *yp = nullptr;
    cudaGetSymbolAddress(&zp, g_z);
    cudaGetSymbolAddress(&yp, g_y);

    // 0-3) build CSR of incoming edges
    zero_kernel<<<(N + 255) / 256, 256>>>(N);
    count_kernel<<<(E + 255) / 256, 256>>>(dst, N, E);
    scan_reduce_kernel<<<nblk, SCAN_B>>>(N);
    scan_top_kernel<<<1, 64>>>(nblk);
    scan_final_kernel<<<nblk, SCAN_B>>>(N);
    scatter_kernel<<<(E + 255) / 256, 256>>>(src, dst, N, E);

    // 4) gather + (1+eps)*h fused
    gather_kernel<<<(N * 32 + 255) / 256, 256>>>(h, eps, N);

    // 5) y = relu(z @ W1 + b1)
    int gblocks = (N + 63) / 64;
    gemm_kernel<<<gblocks, 256, smem>>>((const float*)zp, W1, b1, (float*)yp, N, 1, 0);

    // 6) z = y @ W2 + b2  (+ BN stats fused)
    gemm_kernel<<<gblocks, 256, smem>>>((const float*)yp, W2, b2, (float*)zp, N, 0, 1);

    // 7) fold into scale/shift
    bnfin_kernel<<<1, DIM>>>(gamma, beta, 1.0f / (float)N);

    // 8) out = h + leaky(z*scale + shift)
    ewise_kernel<<<(total4 + 255) / 256, 256>>>(h, (const float*)zp, out, total4);
}

// round 6
// speedup vs baseline: 2.8705x; 1.0253x over previous
#include <cuda_runtime.h>
#include <cuda_fp16.h>

#define DIM 128
#define NODES_MAX 50304
#define EDGES_MAX 1700000
#define SCAN_B 1024
#define SCAN_NBLK ((NODES_MAX + SCAN_B - 1) / SCAN_B)

typedef unsigned long long ull;

// Scratch (static device globals — no runtime allocation allowed)
__device__ __align__(16) float g_z[NODES_MAX * DIM];
__device__ __align__(16) float g_y[NODES_MAX * DIM];
__device__ __align__(16) __half g_h2[NODES_MAX * DIM];
__device__ float g_sum[DIM];
__device__ float g_sq[DIM];
__device__ int g_deg[NODES_MAX];
__device__ int g_off[NODES_MAX];
__device__ int g_cur[NODES_MAX];
__device__ int g_elist[EDGES_MAX];
__device__ volatile int g_sstat[SCAN_NBLK];
__device__ volatile int g_sagg[SCAN_NBLK];
__device__ volatile int g_spre[SCAN_NBLK];

// ---- packed f32x2 helpers (sm_103a FFMA2) ---------------------------------
__device__ __forceinline__ void fma2(ull& acc, ull a, ull b) {
    asm("fma.rn.f32x2 %0, %1, %2, %0;" : "+l"(acc) : "l"(a), "l"(b));
}
__device__ __forceinline__ ull pack2(float x) {
    ull r;
    asm("mov.b64 %0, {%1, %1};" : "=l"(r) : "f"(x));
    return r;
}
__device__ __forceinline__ void unpack2(ull v, float& lo, float& hi) {
    asm("mov.b64 {%0, %1}, %2;" : "=f"(lo), "=f"(hi) : "l"(v));
}

// ---------------------------------------------------------------------------
// 0) zero degree counters, BN accumulators, scan statuses
// ---------------------------------------------------------------------------
__global__ void zero_kernel(int n) {
    int i = blockIdx.x * blockDim.x + threadIdx.x;
    if (i < n) g_deg[i] = 0;
    if (i < DIM) { g_sum[i] = 0.f; g_sq[i] = 0.f; }
    if (i < SCAN_NBLK) g_sstat[i] = 0;
}

// ---------------------------------------------------------------------------
// 1) degree histogram over dst
// ---------------------------------------------------------------------------
__global__ void count_kernel(const int* __restrict__ dst, int nnodes, int E) {
    int e = blockIdx.x * blockDim.x + threadIdx.x;
    if (e >= E) return;
    int d = dst[e];
    if ((unsigned)d < (unsigned)nnodes) atomicAdd(&g_deg[d], 1);
}

// ---------------------------------------------------------------------------
// 1b) h -> fp16 copy (for the gather's neighbor reads)
// ---------------------------------------------------------------------------
__global__ void h2conv_kernel(const float* __restrict__ h, int total4) {
    int i = blockIdx.x * blockDim.x + threadIdx.x;
    if (i >= total4) return;
    float4 v = ((const float4*)h)[i];
    __half2 a = __floats2half2_rn(v.x, v.y);
    __half2 b = __floats2half2_rn(v.z, v.w);
    uint2 u;
    u.x = *(unsigned int*)&a;
    u.y = *(unsigned int*)&b;
    ((uint2*)g_h2)[i] = u;
}

// ---------------------------------------------------------------------------
// 2) single-pass exclusive scan of degrees (decoupled lookback).
//    49 CTAs, all co-resident on 148 SMs -> lookback spin cannot deadlock.
// ---------------------------------------------------------------------------
__global__ void scan_kernel(int n) {
    __shared__ int sm[SCAN_B];
    __shared__ int s_excl;
    int t = threadIdx.x, b = blockIdx.x;
    int i = b * SCAN_B + t;
    int d = (i < n) ? g_deg[i] : 0;
    sm[t] = d;
    __syncthreads();
    for (int s = 1; s < SCAN_B; s <<= 1) {
        int v = (t >= s) ? sm[t - s] : 0;
        __syncthreads();
        sm[t] += v;
        __syncthreads();
    }
    int agg = sm[SCAN_B - 1];
    if (t == 0) {
        if (b == 0) {
            g_spre[0] = agg;
            __threadfence();
            g_sstat[0] = 2;
            s_excl = 0;
        } else {
            g_sagg[b] = agg;
            __threadfence();
            g_sstat[b] = 1;
            int excl = 0;
            int j = b - 1;
            while (true) {
                int st;
                while ((st = g_sstat[j]) == 0) { }
                if (st == 2) { excl += g_spre[j]; break; }
                excl += g_sagg[j];
                j--;
            }
            g_spre[b] = excl + agg;
            __threadfence();
            g_sstat[b] = 2;
            s_excl = excl;
        }
    }
    __syncthreads();
    if (i < n) {
        int e = sm[t] - d + s_excl;
        g_off[i] = e;
        g_cur[i] = e;
    }
}

// ---------------------------------------------------------------------------
// 3) scatter src ids into per-dst segments
// ---------------------------------------------------------------------------
__global__ void scatter_kernel(const int* __restrict__ src,
                               const int* __restrict__ dst, int nnodes, int E) {
    int e = blockIdx.x * blockDim.x + threadIdx.x;
    if (e >= E) return;
    int d = dst[e];
    int s = src[e];
    if ((unsigned)d >= (unsigned)nnodes || (unsigned)s >= (unsigned)nnodes) return;
    int pos = atomicAdd(&g_cur[d], 1);
    g_elist[pos] = s;
}

// ---------------------------------------------------------------------------
// 4) gather: z[u] = (1+eps)*h[u] + sum_{v} h_fp16[v]   (fp32 accumulate)
//    warp per node; lane covers 4 feats (8 bytes fp16 per neighbor).
// ---------------------------------------------------------------------------
__global__ void gather_kernel(const float* __restrict__ h,
                              const float* __restrict__ eps, int nnodes) {
    int warp = (blockIdx.x * blockDim.x + threadIdx.x) >> 5;
    int lane = threadIdx.x & 31;
    if (warp >= nnodes) return;
    int u = warp;
    int off = g_off[u];
    int dg = g_deg[u];

    float4 acc = make_float4(0.f, 0.f, 0.f, 0.f);
    int j = 0;
    for (; j + 32 <= dg; j += 32) {
        int vid = g_elist[off + j + lane];
#pragma unroll
        for (int k = 0; k < 32; k++) {
            int v = __shfl_sync(0xffffffffu, vid, k);
            uint2 uu = *(const uint2*)(g_h2 + (long long)v * DIM + lane * 4);
            __half2 p0 = *(__half2*)&uu.x;
            __half2 p1 = *(__half2*)&uu.y;
            float2 f0 = __half22float2(p0);
            float2 f1 = __half22float2(p1);
            acc.x += f0.x; acc.y += f0.y; acc.z += f1.x; acc.w += f1.y;
        }
    }
    int rem = dg - j;
    if (rem > 0) {
        int vid = (lane < rem) ? g_elist[off + j + lane] : 0;
        for (int k = 0; k < rem; k++) {
            int v = __shfl_sync(0xffffffffu, vid, k);
            uint2 uu = *(const uint2*)(g_h2 + (long long)v * DIM + lane * 4);
            __half2 p0 = *(__half2*)&uu.x;
            __half2 p1 = *(__half2*)&uu.y;
            float2 f0 = __half22float2(p0);
            float2 f1 = __half22float2(p1);
            acc.x += f0.x; acc.y += f0.y; acc.z += f1.x; acc.w += f1.y;
        }
    }
    float e = 1.0f + eps[0];
    float4 hv = *(const float4*)(h + (long long)u * DIM + lane * 4);
    acc.x += e * hv.x; acc.y += e * hv.y; acc.z += e * hv.z; acc.w += e * hv.w;
    *(float4*)(g_z + (long long)u * DIM + lane * 4) = acc;
}

// ---------------------------------------------------------------------------
// 5/6) C = act(A @ W + b) with packed f32x2 FMA; optional BN stats of C.
// ---------------------------------------------------------------------------
__global__ __launch_bounds__(256, 2)
void gemm_kernel(const float* __restrict__ A, const float* __restrict__ W,
                 const float* __restrict__ bias, float* __restrict__ C,
                 int M, int do_relu, int do_stats) {
    extern __shared__ float sm[];
    float* Ws = sm;              // DIM*DIM floats   (64 KB)
    float* As = sm + DIM * DIM;  // 64*DIM floats    (32 KB)
    int tid = threadIdx.x;
    int row0 = blockIdx.x * 64;

    const float4* W4 = (const float4*)W;
    float4* Ws4 = (float4*)Ws;
#pragma unroll
    for (int i = 0; i < 16; i++) Ws4[tid + 256 * i] = W4[tid + 256 * i];

    float4* As4 = (float4*)As;
#pragma unroll
    for (int i = 0; i < 8; i++) {
        int idx = tid + 256 * i;
        int r = idx >> 5;
        int c = idx & 31;
        float4 v = make_float4(0.f, 0.f, 0.f, 0.f);
        int gr = row0 + r;
        if (gr < M) v = ((const float4*)A)[(long long)gr * 32 + c];
        As4[idx] = v;
    }
    __syncthreads();

    int cg = tid & 31;   // column group -> cols [4cg, 4cg+4)
    int rg = tid >> 5;   // row group    -> rows [rg*8, rg*8+8)

    ull acc2[8][2];
#pragma unroll
    for (int i = 0; i < 8; i++) { acc2[i][0] = 0ull; acc2[i][1] = 0ull; }

    const float* Ar = As + rg * 8 * DIM;
#pragma unroll 4
    for (int k = 0; k < DIM; k += 4) {
        double2 w0 = *(const double2*)(Ws + (k + 0) * DIM + cg * 4);
        double2 w1 = *(const double2*)(Ws + (k + 1) * DIM + cg * 4);
        double2 w2 = *(const double2*)(Ws + (k + 2) * DIM + cg * 4);
        double2 w3 = *(const double2*)(Ws + (k + 3) * DIM + cg * 4);
        ull w0l = __double_as_longlong(w0.x), w0h = __double_as_longlong(w0.y);
        ull w1l = __double_as_longlong(w1.x), w1h = __double_as_longlong(w1.y);
        ull w2l = __double_as_longlong(w2.x), w2h = __double_as_longlong(w2.y);
        ull w3l = __double_as_longlong(w3.x), w3h = __double_as_longlong(w3.y);
#pragma unroll
        for (int i = 0; i < 8; i++) {
            float4 a = *(const float4*)(Ar + i * DIM + k);  // warp-broadcast
            ull ax = pack2(a.x), ay = pack2(a.y), az = pack2(a.z), aw = pack2(a.w);
            fma2(acc2[i][0], ax, w0l); fma2(acc2[i][1], ax, w0h);
            fma2(acc2[i][0], ay, w1l); fma2(acc2[i][1], ay, w1h);
            fma2(acc2[i][0], az, w2l); fma2(acc2[i][1], az, w2h);
            fma2(acc2[i][0], aw, w3l); fma2(acc2[i][1], aw, w3h);
        }
    }

    float4 b4 = ((const float4*)bias)[cg];
    float s4[4] = {0.f, 0.f, 0.f, 0.f};
    float q4[4] = {0.f, 0.f, 0.f, 0.f};
#pragma unroll
    for (int i = 0; i < 8; i++) {
        int gr = row0 + rg * 8 + i;
        if (gr < M) {
            float4 o;
            unpack2(acc2[i][0], o.x, o.y);
            unpack2(acc2[i][1], o.z, o.w);
            o.x += b4.x; o.y += b4.y; o.z += b4.z; o.w += b4.w;
            if (do_relu) {
                o.x = fmaxf(o.x, 0.f); o.y = fmaxf(o.y, 0.f);
                o.z = fmaxf(o.z, 0.f); o.w = fmaxf(o.w, 0.f);
            }
            s4[0] += o.x; s4[1] += o.y; s4[2] += o.z; s4[3] += o.w;
            q4[0] += o.x * o.x; q4[1] += o.y * o.y;
            q4[2] += o.z * o.z; q4[3] += o.w * o.w;
            ((float4*)(C + (long long)gr * DIM))[cg] = o;
        }
    }

    if (do_stats) {
        __syncthreads();  // done reading As
        float* Ss = As;          // [128 cols][8 rg]
        float* Qs = As + 1024;   // [128 cols][8 rg]
#pragma unroll
        for (int c = 0; c < 4; c++) {
            Ss[(cg * 4 + c) * 8 + rg] = s4[c];
            Qs[(cg * 4 + c) * 8 + rg] = q4[c];
        }
        __syncthreads();
        if (tid < DIM) {
            float s = 0.f, q = 0.f;
#pragma unroll
            for (int r = 0; r < 8; r++) {
                s += Ss[tid * 8 + r];
                q += Qs[tid * 8 + r];
            }
            atomicAdd(&g_sum[tid], s);
            atomicAdd(&g_sq[tid], q);
        }
    }
}

// ---------------------------------------------------------------------------
// 7) out = h + leaky_relu(z*scale + shift)  (BN fold fused, per-block)
// ---------------------------------------------------------------------------
__global__ void ewise_kernel(const float* __restrict__ h,
                             const float* __restrict__ Z,
                             const float* __restrict__ gamma,
                             const float* __restrict__ beta,
                             float* __restrict__ out, int total4, float invN) {
    __shared__ float ssc[DIM], ssh[DIM];
    int t = threadIdx.x;
    if (t < DIM) {
        float mean = g_sum[t] * invN;
        float var = g_sq[t] * invN - mean * mean;
        float sc = gamma[t] * rsqrtf(var + 1e-5f);
        ssc[t] = sc;
        ssh[t] = beta[t] - mean * sc;
    }
    __syncthreads();
    int i = blockIdx.x * blockDim.x + t;
    if (i >= total4) return;
    int cg = i & 31;
    float4 sc = ((const float4*)ssc)[cg];
    float4 sh = ((const float4*)ssh)[cg];
    float4 zv = ((const float4*)Z)[i];
    float4 hv = ((const float4*)h)[i];
    float x;
    float4 o;
    x = zv.x * sc.x + sh.x; o.x = hv.x + (x >= 0.f ? x : 0.01f * x);
    x = zv.y * sc.y + sh.y; o.y = hv.y + (x >= 0.f ? x : 0.01f * x);
    x = zv.z * sc.z + sh.z; o.z = hv.z + (x >= 0.f ? x : 0.01f * x);
    x = zv.w * sc.w + sh.w; o.w = hv.w + (x >= 0.f ? x : 0.01f * x);
    ((float4*)out)[i] = o;
}

// ---------------------------------------------------------------------------
extern "C" void kernel_launch(void* const* d_in, const int* in_sizes, int n_in,
                              void* d_out, int out_size) {
    const float* h     = (const float*)d_in[0];
    const int*   src   = (const int*)d_in[1];
    const int*   dst   = (const int*)d_in[2];
    const float* eps   = (const float*)d_in[3];
    const float* W1    = (const float*)d_in[4];
    const float* b1    = (const float*)d_in[5];
    const float* W2    = (const float*)d_in[6];
    const float* b2    = (const float*)d_in[7];
    const float* gamma = (const float*)d_in[8];
    const float* beta  = (const float*)d_in[9];
    float* out = (float*)d_out;

    int N = in_sizes[0] / DIM;
    int E = in_sizes[1];
    int total4 = N * (DIM / 4);
    int nblk = (N + SCAN_B - 1) / SCAN_B;

    size_t smem = (size_t)(DIM * DIM + 64 * DIM) * sizeof(float);  // 96 KB
    cudaFuncSetAttribute(gemm_kernel,
                         cudaFuncAttributeMaxDynamicSharedMemorySize,
                         (int)smem);

    void *zp = nullptr, *yp = nullptr;
    cudaGetSymbolAddress(&zp, g_z);
    cudaGetSymbolAddress(&yp, g_y);

    // 0-3) build CSR of incoming edges (+ fp16 copy of h)
    zero_kernel<<<(N + 255) / 256, 256>>>(N);
    count_kernel<<<(E + 255) / 256, 256>>>(dst, N, E);
    h2conv_kernel<<<(total4 + 255) / 256, 256>>>(h, total4);
    scan_kernel<<<nblk, SCAN_B>>>(N);
    scatter_kernel<<<(E + 255) / 256, 256>>>(src, dst, N, E);

    // 4) gather + (1+eps)*h fused
    gather_kernel<<<(N * 32 + 255) / 256, 256>>>(h, eps, N);

    // 5) y = relu(z @ W1 + b1)
    int gblocks = (N + 63) / 64;
    gemm_kernel<<<gblocks, 256, smem>>>((const float*)zp, W1, b1, (float*)yp, N, 1, 0);

    // 6) z = y @ W2 + b2  (+ BN stats fused)
    gemm_kernel<<<gblocks, 256, smem>>>((const float*)yp, W2, b2, (float*)zp, N, 0, 1);

    // 7) out = h + leaky(z*scale + shift)  (BN fold fused)
    ewise_kernel<<<(total4 + 255) / 256, 256>>>(h, (const float*)zp, gamma, beta,
                                                out, total4, 1.0f / (float)N);
}

// round 9
// speedup vs baseline: 4.3274x; 1.5076x over previous
#include <cuda_runtime.h>
#include <cuda_fp16.h>
#include <cstdint>

#define DIM 128
#define NODES_MAX 50304
#define EDGES_MAX 1700000
#define SCAN_B 1024
#define SCAN_NBLK 50

typedef unsigned long long ull;

// ---------------- scratch (static device globals) --------------------------
__device__ __align__(16) float  g_z[NODES_MAX * DIM];   // z2 fp32 (GEMM2 out)
__device__ __align__(16) __half g_h2[NODES_MAX * DIM];  // h fp16 (gather reads)
__device__ __align__(16) __half g_zh[NODES_MAX * DIM];  // z fp16 (gather out / GEMM1 A)
__device__ __align__(16) __half g_yh[NODES_MAX * DIM];  // y fp16 (GEMM1 out / GEMM2 A)
__device__ __align__(16) __half g_w1h[DIM * DIM];       // W1 fp16 (K-major, as-is)
__device__ __align__(16) __half g_w2h[DIM * DIM];       // W2 fp16
__device__ float g_sum[DIM];
__device__ float g_sq[DIM];
__device__ int g_deg[NODES_MAX];
__device__ int g_off[NODES_MAX];
__device__ int g_cur[NODES_MAX];
__device__ int g_elist[EDGES_MAX];
__device__ volatile int g_sstat[SCAN_NBLK];
__device__ volatile int g_sagg[SCAN_NBLK];
__device__ volatile int g_spre[SCAN_NBLK];

// ---------------- mma.sync helpers (base ISA, runs on tensor cores) --------
__device__ __forceinline__ uint32_t smem_u32(const void* p) {
    uint32_t a;
    asm("{ .reg .u64 t; cvta.to.shared.u64 t, %1; cvt.u32.u64 %0, t; }"
        : "=r"(a) : "l"(p));
    return a;
}
__device__ __forceinline__ void ldsm4(uint32_t* r, uint32_t addr) {
    asm volatile("ldmatrix.sync.aligned.m8n8.x4.shared.b16 {%0,%1,%2,%3}, [%4];"
                 : "=r"(r[0]), "=r"(r[1]), "=r"(r[2]), "=r"(r[3]) : "r"(addr));
}
__device__ __forceinline__ void ldsm4t(uint32_t* r, uint32_t addr) {
    asm volatile("ldmatrix.sync.aligned.m8n8.x4.trans.shared.b16 {%0,%1,%2,%3}, [%4];"
                 : "=r"(r[0]), "=r"(r[1]), "=r"(r[2]), "=r"(r[3]) : "r"(addr));
}
__device__ __forceinline__ void mma16816(float* c, const uint32_t* a,
                                         uint32_t b0, uint32_t b1) {
    asm volatile(
        "mma.sync.aligned.m16n8k16.row.col.f32.f16.f16.f32 "
        "{%0,%1,%2,%3}, {%4,%5,%6,%7}, {%8,%9}, {%0,%1,%2,%3};"
        : "+f"(c[0]), "+f"(c[1]), "+f"(c[2]), "+f"(c[3])
        : "r"(a[0]), "r"(a[1]), "r"(a[2]), "r"(a[3]), "r"(b0), "r"(b1));
}

// ---------------------------------------------------------------------------
// 0) zero degree counters, BN accumulators, scan statuses
// ---------------------------------------------------------------------------
__global__ void zero_kernel(int n) {
    int i = blockIdx.x * blockDim.x + threadIdx.x;
    if (i < n) g_deg[i] = 0;
    if (i < DIM) { g_sum[i] = 0.f; g_sq[i] = 0.f; }
    if (i < SCAN_NBLK) g_sstat[i] = 0;
}

// ---------------------------------------------------------------------------
// 1) prep: degree histogram + h->fp16 + W1/W2 -> fp16 (no transpose)
// ---------------------------------------------------------------------------
__global__ void prep_kernel(const int* __restrict__ dst,
                            const float* __restrict__ W1,
                            const float* __restrict__ W2,
                            const float* __restrict__ h,
                            int nnodes, int E, int total4) {
    int i = blockIdx.x * blockDim.x + threadIdx.x;
    if (i < E) {
        int d = dst[i];
        if ((unsigned)d < (unsigned)nnodes) atomicAdd(&g_deg[d], 1);
    }
    if (i < total4) {
        float4 v = ((const float4*)h)[i];
        __half2 a = __floats2half2_rn(v.x, v.y);
        __half2 b = __floats2half2_rn(v.z, v.w);
        uint2 u;
        u.x = *(unsigned int*)&a;
        u.y = *(unsigned int*)&b;
        ((uint2*)g_h2)[i] = u;
    }
    if (i < 2 * DIM * DIM) {
        int w = i >> 14;            // 0 -> W1, 1 -> W2
        int idx = i & 16383;
        float val = w ? W2[idx] : W1[idx];
        __half hv = __float2half_rn(val);
        if (w) g_w2h[idx] = hv;
        else   g_w1h[idx] = hv;
    }
}

// ---------------------------------------------------------------------------
// 2) single-pass exclusive scan (warp-parallel decoupled lookback).
//    49 CTAs, all co-resident on 148 SMs -> spins cannot deadlock.
// ---------------------------------------------------------------------------
__global__ void scan_kernel(int n) {
    __shared__ int wsum[32];
    __shared__ int s_excl;
    int t = threadIdx.x, b = blockIdx.x;
    int i = b * SCAN_B + t;
    int d = (i < n) ? g_deg[i] : 0;
    int lane = t & 31, w = t >> 5;
    int v = d;
#pragma unroll
    for (int s = 1; s < 32; s <<= 1) {
        int u = __shfl_up_sync(0xffffffffu, v, s);
        if (lane >= s) v += u;
    }
    if (lane == 31) wsum[w] = v;
    __syncthreads();
    if (w == 0) {
        int x = wsum[lane];
#pragma unroll
        for (int s = 1; s < 32; s <<= 1) {
            int u = __shfl_up_sync(0xffffffffu, x, s);
            if (lane >= s) x += u;
        }
        wsum[lane] = x;
    }
    __syncthreads();
    int incl = v + (w ? wsum[w - 1] : 0);
    int agg = wsum[31];

    if (t == 0) {
        if (b == 0) {
            g_spre[0] = agg; __threadfence(); g_sstat[0] = 2; s_excl = 0;
        } else {
            g_sagg[b] = agg; __threadfence(); g_sstat[b] = 1;
        }
    }
    if (b > 0 && w == 0) {
        int excl = 0;
        int pos = b;
        while (pos > 0) {
            int j = pos - 1 - lane;
            int st = (j >= 0) ? g_sstat[j] : 2;
            unsigned nr = __ballot_sync(0xffffffffu, st == 0);
            unsigned dn = __ballot_sync(0xffffffffu, st == 2);
            int fd = dn ? (__ffs(dn) - 1) : 32;
            int fnr = nr ? (__ffs(nr) - 1) : 32;
            if (fd < fnr) {
                __threadfence();
                int vl = 0;
                if (j >= 0 && lane <= fd) vl = (lane == fd) ? g_spre[j] : g_sagg[j];
                int contrib = (lane <= fd) ? vl : 0;
#pragma unroll
                for (int s = 16; s > 0; s >>= 1)
                    contrib += __shfl_xor_sync(0xffffffffu, contrib, s);
                excl += contrib;
                pos = 0;
            } else if (fnr == 32) {
                __threadfence();
                int contrib = (j >= 0) ? g_sagg[j] : 0;
#pragma unroll
                for (int s = 16; s > 0; s >>= 1)
                    contrib += __shfl_xor_sync(0xffffffffu, contrib, s);
                excl += contrib;
                pos -= 32;
            }
        }
        if (lane == 0) {
            g_spre[b] = excl + agg;
            __threadfence();
            g_sstat[b] = 2;
            s_excl = excl;
        }
    }
    __syncthreads();
    if (i < n) {
        int e = incl - d + s_excl;
        g_off[i] = e;
        g_cur[i] = e;
    }
}

// ---------------------------------------------------------------------------
// 3) scatter src ids into per-dst segments
// ---------------------------------------------------------------------------
__global__ void scatter_kernel(const int* __restrict__ src,
                               const int* __restrict__ dst, int nnodes, int E) {
    int e = blockIdx.x * blockDim.x + threadIdx.x;
    if (e >= E) return;
    int d = dst[e];
    int s = src[e];
    if ((unsigned)d >= (unsigned)nnodes || (unsigned)s >= (unsigned)nnodes) return;
    int pos = atomicAdd(&g_cur[d], 1);
    g_elist[pos] = s;
}

// ---------------------------------------------------------------------------
// 4) gather: z[u] = (1+eps)*h[u] + sum_v h_fp16[v]; writes z as fp16
// ---------------------------------------------------------------------------
__global__ void gather_kernel(const float* __restrict__ h,
                              const float* __restrict__ eps, int nnodes) {
    int warp = (blockIdx.x * blockDim.x + threadIdx.x) >> 5;
    int lane = threadIdx.x & 31;
    if (warp >= nnodes) return;
    int u = warp;
    int off = g_off[u];
    int dg = g_deg[u];

    float4 acc = make_float4(0.f, 0.f, 0.f, 0.f);
    int j = 0;
    for (; j + 32 <= dg; j += 32) {
        int vid = g_elist[off + j + lane];
#pragma unroll
        for (int k = 0; k < 32; k++) {
            int v = __shfl_sync(0xffffffffu, vid, k);
            uint2 uu = *(const uint2*)(g_h2 + (long long)v * DIM + lane * 4);
            __half2 p0 = *(__half2*)&uu.x;
            __half2 p1 = *(__half2*)&uu.y;
            float2 f0 = __half22float2(p0);
            float2 f1 = __half22float2(p1);
            acc.x += f0.x; acc.y += f0.y; acc.z += f1.x; acc.w += f1.y;
        }
    }
    int rem = dg - j;
    if (rem > 0) {
        int vid = (lane < rem) ? g_elist[off + j + lane] : 0;
        for (int k = 0; k < rem; k++) {
            int v = __shfl_sync(0xffffffffu, vid, k);
            uint2 uu = *(const uint2*)(g_h2 + (long long)v * DIM + lane * 4);
            __half2 p0 = *(__half2*)&uu.x;
            __half2 p1 = *(__half2*)&uu.y;
            float2 f0 = __half22float2(p0);
            float2 f1 = __half22float2(p1);
            acc.x += f0.x; acc.y += f0.y; acc.z += f1.x; acc.w += f1.y;
        }
    }
    float e = 1.0f + eps[0];
    float4 hv = *(const float4*)(h + (long long)u * DIM + lane * 4);
    acc.x += e * hv.x; acc.y += e * hv.y; acc.z += e * hv.z; acc.w += e * hv.w;
    __half2 o0 = __floats2half2_rn(acc.x, acc.y);
    __half2 o1 = __floats2half2_rn(acc.z, acc.w);
    uint2 ou;
    ou.x = *(unsigned int*)&o0;
    ou.y = *(unsigned int*)&o1;
    *(uint2*)(g_zh + (long long)u * DIM + lane * 4) = ou;
}

// ---------------------------------------------------------------------------
// 5/6) HMMA GEMM: 64-row x 128-col tile per 128-thread block (4 warps).
//   C = A(fp16) @ W(fp16) + b, fp32 accum via mma.sync.m16n8k16.
//   mode 0: relu -> fp16 out.   mode 1: fp32 out + fused BN column stats.
//   smem: A 64x128 fp16 (272B row stride), W 128x128 fp16 (272B stride).
// ---------------------------------------------------------------------------
#define MMA_STRIDE 272
#define SM_A_SZ (64 * MMA_STRIDE)     // 17408
#define SM_B_OFF SM_A_SZ
#define SMEM_GEMM (SM_A_SZ + 128 * MMA_STRIDE)  // 52224

__global__ __launch_bounds__(128)
void mma_kernel(const __half* __restrict__ A, const __half* __restrict__ B,
                const float* __restrict__ bias, __half* __restrict__ outh,
                float* __restrict__ outf, int M, int mode) {
    extern __shared__ char smem[];
    __shared__ float sbias[DIM];
    __shared__ float sS[4][DIM];
    __shared__ float sQ[4][DIM];

    int tid = threadIdx.x, wid = tid >> 5, lane = tid & 31;
    int tig = lane & 3, gid = lane >> 2;
    int row0 = blockIdx.x * 64;

    sbias[tid] = bias[tid];

    // load A tile (64 x 128 fp16) and W (128 x 128 fp16) into padded smem
    const uint4* A4 = (const uint4*)A;
    const uint4* B4 = (const uint4*)B;
#pragma unroll
    for (int j = 0; j < 8; j++) {
        int idx = tid + 128 * j;            // 1024 chunks of 16B
        int r = idx >> 4, i = idx & 15;
        uint4 v = make_uint4(0, 0, 0, 0);
        if (row0 + r < M) v = A4[(long long)(row0 + r) * 16 + i];
        *(uint4*)(smem + r * MMA_STRIDE + i * 16) = v;
    }
#pragma unroll
    for (int j = 0; j < 16; j++) {
        int idx = tid + 128 * j;            // 2048 chunks
        int r = idx >> 4, i = idx & 15;
        *(uint4*)(smem + SM_B_OFF + r * MMA_STRIDE + i * 16) = B4[idx];
    }
    __syncthreads();

    uint32_t sA = smem_u32(smem);
    uint32_t sB = sA + SM_B_OFF;
    uint32_t aAddr = sA + (wid * 16 + (lane & 15)) * MMA_STRIDE + (lane >> 4) * 16;
    uint32_t bAddr = sB + (lane & 15) * MMA_STRIDE + (lane >> 4) * 16;

    float acc[16][4];
#pragma unroll
    for (int i = 0; i < 16; i++) {
        acc[i][0] = 0.f; acc[i][1] = 0.f; acc[i][2] = 0.f; acc[i][3] = 0.f;
    }

#pragma unroll
    for (int k0 = 0; k0 < DIM; k0 += 16) {
        uint32_t af[4];
        ldsm4(af, aAddr + k0 * 2);
#pragma unroll
        for (int p = 0; p < 8; p++) {
            uint32_t bf[4];
            ldsm4t(bf, bAddr + k0 * MMA_STRIDE + p * 32);
            mma16816(acc[2 * p],     af, bf[0], bf[1]);
            mma16816(acc[2 * p + 1], af, bf[2], bf[3]);
        }
    }

    int rowA = row0 + wid * 16 + gid;
    int rowB = rowA + 8;
    bool vA = rowA < M, vB = rowB < M;

    if (mode == 0) {
#pragma unroll
        for (int nt = 0; nt < 16; nt++) {
            int col = nt * 8 + 2 * tig;
            float b0 = sbias[col], b1 = sbias[col + 1];
            float v0 = fmaxf(acc[nt][0] + b0, 0.f);
            float v1 = fmaxf(acc[nt][1] + b1, 0.f);
            float v2 = fmaxf(acc[nt][2] + b0, 0.f);
            float v3 = fmaxf(acc[nt][3] + b1, 0.f);
            if (vA) *(__half2*)(outh + (long long)rowA * DIM + col) = __floats2half2_rn(v0, v1);
            if (vB) *(__half2*)(outh + (long long)rowB * DIM + col) = __floats2half2_rn(v2, v3);
        }
    } else {
#pragma unroll
        for (int nt = 0; nt < 16; nt++) {
            int col = nt * 8 + 2 * tig;
            float b0 = sbias[col], b1 = sbias[col + 1];
            float v0 = vA ? (acc[nt][0] + b0) : 0.f;
            float v1 = vA ? (acc[nt][1] + b1) : 0.f;
            float v2 = vB ? (acc[nt][2] + b0) : 0.f;
            float v3 = vB ? (acc[nt][3] + b1) : 0.f;
            if (vA) *(float2*)(outf + (long long)rowA * DIM + col) = make_float2(v0, v1);
            if (vB) *(float2*)(outf + (long long)rowB * DIM + col) = make_float2(v2, v3);
            // column partials over this warp's 16 rows (reduce across gid lanes)
            float sE = v0 + v2, qE = v0 * v0 + v2 * v2;
            float sO = v1 + v3, qO = v1 * v1 + v3 * v3;
#pragma unroll
            for (int m = 4; m < 32; m <<= 1) {
                sE += __shfl_xor_sync(0xffffffffu, sE, m);
                qE += __shfl_xor_sync(0xffffffffu, qE, m);
                sO += __shfl_xor_sync(0xffffffffu, sO, m);
                qO += __shfl_xor_sync(0xffffffffu, qO, m);
            }
            if (gid == 0) {
                sS[wid][col] = sE;     sQ[wid][col] = qE;
                sS[wid][col + 1] = sO; sQ[wid][col + 1] = qO;
            }
        }
        __syncthreads();
        float s = sS[0][tid] + sS[1][tid] + sS[2][tid] + sS[3][tid];
        float q = sQ[0][tid] + sQ[1][tid] + sQ[2][tid] + sQ[3][tid];
        atomicAdd(&g_sum[tid], s);
        atomicAdd(&g_sq[tid], q);
    }
}

// ---------------------------------------------------------------------------
// 7) out = h + leaky_relu(z*scale + shift)  (BN fold fused per block)
// ---------------------------------------------------------------------------
__global__ void ewise_kernel(const float* __restrict__ h,
                             const float* __restrict__ Z,
                             const float* __restrict__ gamma,
                             const float* __restrict__ beta,
                             float* __restrict__ out, int total4, float invN) {
    __shared__ float ssc[DIM], ssh[DIM];
    int t = threadIdx.x;
    if (t < DIM) {
        float mean = g_sum[t] * invN;
        float var = g_sq[t] * invN - mean * mean;
        float sc = gamma[t] * rsqrtf(var + 1e-5f);
        ssc[t] = sc;
        ssh[t] = beta[t] - mean * sc;
    }
    __syncthreads();
    int i = blockIdx.x * blockDim.x + t;
    if (i >= total4) return;
    int cg = i & 31;
    float4 sc = ((const float4*)ssc)[cg];
    float4 sh = ((const float4*)ssh)[cg];
    float4 zv = ((const float4*)Z)[i];
    float4 hv = ((const float4*)h)[i];
    float x;
    float4 o;
    x = zv.x * sc.x + sh.x; o.x = hv.x + (x >= 0.f ? x : 0.01f * x);
    x = zv.y * sc.y + sh.y; o.y = hv.y + (x >= 0.f ? x : 0.01f * x);
    x = zv.z * sc.z + sh.z; o.z = hv.z + (x >= 0.f ? x : 0.01f * x);
    x = zv.w * sc.w + sh.w; o.w = hv.w + (x >= 0.f ? x : 0.01f * x);
    ((float4*)out)[i] = o;
}

// ---------------------------------------------------------------------------
extern "C" void kernel_launch(void* const* d_in, const int* in_sizes, int n_in,
                              void* d_out, int out_size) {
    const float* h     = (const float*)d_in[0];
    const int*   src   = (const int*)d_in[1];
    const int*   dst   = (const int*)d_in[2];
    const float* eps   = (const float*)d_in[3];
    const float* W1    = (const float*)d_in[4];
    const float* b1    = (const float*)d_in[5];
    const float* W2    = (const float*)d_in[6];
    const float* b2    = (const float*)d_in[7];
    const float* gamma = (const float*)d_in[8];
    const float* beta  = (const float*)d_in[9];
    float* out = (float*)d_out;

    int N = in_sizes[0] / DIM;
    int E = in_sizes[1];
    int total4 = N * (DIM / 4);
    int nblk = (N + SCAN_B - 1) / SCAN_B;

    cudaFuncSetAttribute(mma_kernel,
                         cudaFuncAttributeMaxDynamicSharedMemorySize, SMEM_GEMM);

    void *zp = nullptr, *zhp = nullptr, *yhp = nullptr, *w1p = nullptr, *w2p = nullptr;
    cudaGetSymbolAddress(&zp, g_z);
    cudaGetSymbolAddress(&zhp, g_zh);
    cudaGetSymbolAddress(&yhp, g_yh);
    cudaGetSymbolAddress(&w1p, g_w1h);
    cudaGetSymbolAddress(&w2p, g_w2h);

    int prepwork = (E > total4) ? E : total4;

    // 0-3) build CSR of incoming edges + fp16 conversions
    zero_kernel<<<(N + 255) / 256, 256>>>(N);
    prep_kernel<<<(prepwork + 255) / 256, 256>>>(dst, W1, W2, h, N, E, total4);
    scan_kernel<<<nblk, SCAN_B>>>(N);
    scatter_kernel<<<(E + 255) / 256, 256>>>(src, dst, N, E);

    // 4) gather (fp16 z out)
    gather_kernel<<<(N * 32 + 255) / 256, 256>>>(h, eps, N);

    // 5) y = relu(z @ W1 + b1)   (fp16 out)
    int gblocks = (N + 63) / 64;
    mma_kernel<<<gblocks, 128, SMEM_GEMM>>>((const __half*)zhp, (const __half*)w1p,
                                            b1, (__half*)yhp, (float*)zp, N, 0);

    // 6) z2 = y @ W2 + b2  (fp32 out + fused BN stats)
    mma_kernel<<<gblocks, 128, SMEM_GEMM>>>((const __half*)yhp, (const __half*)w2p,
                                            b2, (__half*)yhp, (float*)zp, N, 1);

    // 7) out = h + leaky(z2*scale + shift)
    ewise_kernel<<<(total4 + 255) / 256, 256>>>(h, (const float*)zp, gamma, beta,
                                                out, total4, 1.0f / (float)N);
}